// round 12
// baseline (speedup 1.0000x reference)
#include <cuda_runtime.h>
#include <cuda_fp16.h>
#include <math.h>

#define NN 100000
#define EE 1600000
#define KE 64
#define INC 128
#define HID 256
#define OC 16

typedef unsigned long long ull;

// ---- static device scratch ----
__device__ __half  g_Wh[(size_t)NN * KE];  // MLP_W^T fp16 [N,64]
__device__ float   g_S [(size_t)NN * KE];  // S fp32
__device__ __half  g_Sh[(size_t)NN * KE];  // S fp16 (cut-phase gather)
__device__ int     g_deg[NN];
__device__ int     g_ptr[NN + 1];
__device__ int     g_pos[NN];
__device__ int     g_srt[EE];
__device__ int     g_ord[NN];              // node ids sorted by degree
__device__ int     g_dhist[64];
__device__ int     g_dpos[64];
__device__ int     g_bsum[128];
__device__ float   g_SS[KE * KE];
__device__ float   g_Wc[OC * INC];
__device__ float   g_bc[OC];
__device__ double  g_cut;
__device__ double  g_dt;
__device__ volatile unsigned g_bar;

// ---- software grid barrier: grid <= guaranteed-resident blocks ----
__device__ __forceinline__ void gsync(unsigned target) {
    __syncthreads();
    if (threadIdx.x == 0) {
        __threadfence();
        atomicAdd((unsigned*)&g_bar, 1u);
        while (g_bar < target) __nanosleep(64);
        __threadfence();
    }
    __syncthreads();
}

__device__ __forceinline__ void cvt8(float4 u, float* p) {
    float2 c0 = __half22float2(*(__half2*)&u.x);
    float2 c1 = __half22float2(*(__half2*)&u.y);
    float2 c2 = __half22float2(*(__half2*)&u.z);
    float2 c3 = __half22float2(*(__half2*)&u.w);
    p[0] = c0.x; p[1] = c0.y; p[2] = c1.x; p[3] = c1.y;
    p[4] = c2.x; p[5] = c2.y; p[6] = c3.x; p[7] = c3.y;
}

__global__ void __launch_bounds__(256) k_persist(
    const float* __restrict__ W,        // MLP_W [64,N]
    const int*   __restrict__ row,
    const int*   __restrict__ col,
    const float* __restrict__ MLPb,
    const float* __restrict__ finW,
    const float* __restrict__ mlpxW,
    const float* __restrict__ mlpxb,
    const float* __restrict__ finb,
    const float* __restrict__ x,
    float*       __restrict__ out,
    int outIdx)
{
    const unsigned G = gridDim.x;
    const int bid = blockIdx.x;
    const int t   = threadIdx.x;
    const int tid = bid * 256 + t;
    const int stride = G * 256;

    __shared__ float  s_tile[32][33];
    __shared__ int    s_scan[256];
    __shared__ int    s_exc[128];
    __shared__ double s_red[32];
    __shared__ float4 s_rows[16][16];
    __shared__ float4 s_Wx[32][16];
    __shared__ float4 s_Wa[16][16];
    __shared__ float  s_bo[16];
    __shared__ double s_loss[256];
    __shared__ double s_dnrm;

    // ================= P0: hist | transpose->fp16 | wcomb | zero small =================
    if (bid == 0) {
        for (int i = t; i < KE * KE; i += 256) g_SS[i] = 0.f;
        if (t < 64) { g_dhist[t] = 0; g_dpos[t] = 0; }
        if (t == 0) { g_cut = 0.0; g_dt = 0.0; }
    }
    for (int e = tid; e < EE; e += stride) atomicAdd(&g_deg[col[e]], 1);
    for (int tb = bid; tb < 6250; tb += (int)G) {
        int v0 = (tb % 3125) * 32, k0 = (tb / 3125) * 32;
        int tx = t & 31, ty = t >> 5;
        __syncthreads();
        #pragma unroll
        for (int r = ty; r < 32; r += 8)
            s_tile[r][tx] = W[(size_t)(k0 + r) * NN + v0 + tx];
        __syncthreads();
        #pragma unroll
        for (int r = ty; r < 32; r += 8)
            g_Wh[(size_t)(v0 + r) * KE + k0 + tx] = __float2half(s_tile[tx][r]);
    }
    for (int idx = tid; idx < OC * INC; idx += stride) {
        int o = idx >> 7, c = idx & 127;
        float s = 0.f;
        for (int h = 0; h < HID; h++) s += finW[o * 320 + h] * mlpxW[h * INC + c];
        g_Wc[idx] = s;
    }
    if (tid < OC) {
        float s = finb[tid];
        for (int h = 0; h < HID; h++) s += finW[tid * 320 + h] * mlpxb[h];
        g_bc[tid] = s;
    }
    gsync(1u * G);

    // ================= P1: per-chunk scan (98 chunks)  +  degree-bin histogram =================
    for (int c = bid; c < 98; c += (int)G) {
        int base = c * 1024 + t * 4;
        int v0 = (base + 0 < NN) ? g_deg[base + 0] : 0;
        int v1 = (base + 1 < NN) ? g_deg[base + 1] : 0;
        int v2 = (base + 2 < NN) ? g_deg[base + 2] : 0;
        int v3 = (base + 3 < NN) ? g_deg[base + 3] : 0;
        int s = v0 + v1 + v2 + v3;
        s_scan[t] = s; __syncthreads();
        for (int off = 1; off < 256; off <<= 1) {
            int xv = (t >= off) ? s_scan[t - off] : 0;
            __syncthreads();
            s_scan[t] += xv;
            __syncthreads();
        }
        int run = s_scan[t] - s;
        if (t == 255) g_bsum[c] = s_scan[255];
        if (base + 0 < NN) g_ptr[base + 0] = run; run += v0;
        if (base + 1 < NN) g_ptr[base + 1] = run; run += v1;
        if (base + 2 < NN) g_ptr[base + 2] = run; run += v2;
        if (base + 3 < NN) g_ptr[base + 3] = run;
    }
    // degree-bin histogram (64 bins, cap at 63)
    for (int i = tid; i < NN; i += stride) {
        int b = g_deg[i]; if (b > 63) b = 63;
        atomicAdd(&g_dhist[b], 1);
    }
    gsync(2u * G);

    // ================= P2: redundant block-sum scan + apply offsets + degree sort =================
    {
        int v = (t < 98) ? g_bsum[t] : 0;
        if (t < 128) s_scan[t] = v;
        __syncthreads();
        for (int off = 1; off < 128; off <<= 1) {
            int xv = 0;
            if (t < 128 && t >= off) xv = s_scan[t - off];
            __syncthreads();
            if (t < 128) s_scan[t] += xv;
            __syncthreads();
        }
        if (t < 128) s_exc[t] = s_scan[t] - v;
        __syncthreads();
        for (int i = tid; i < NN; i += stride) {
            int p = g_ptr[i] + s_exc[i >> 10];
            g_ptr[i] = p;
            g_pos[i] = p;
        }
        if (tid == 0) g_ptr[NN] = EE;
        // ---- counting-sort scatter: node ids ordered by degree bin ----
        __syncthreads();
        int hv = (t < 64) ? g_dhist[t] : 0;
        if (t < 64) s_scan[t] = hv;
        __syncthreads();
        for (int off = 1; off < 64; off <<= 1) {
            int xv = 0;
            if (t < 64 && t >= off) xv = s_scan[t - off];
            __syncthreads();
            if (t < 64) s_scan[t] += xv;
            __syncthreads();
        }
        if (t < 64) s_exc[t] = s_scan[t] - hv;   // exclusive bin base
        __syncthreads();
        for (int i = tid; i < NN; i += stride) {
            int b = g_deg[i]; if (b > 63) b = 63;
            int p = s_exc[b] + atomicAdd(&g_dpos[b], 1);
            g_ord[p] = i;
        }
    }
    gsync(3u * G);

    // ================= P3: scatter edges into CSR =================
    for (int e = tid; e < EE; e += stride) {
        int p = atomicAdd(&g_pos[col[e]], 1);
        g_srt[p] = row[e];
    }
    gsync(4u * G);

    // ================= P4: SpMM1 + softmax + deg_term (quarter-warp/node, degree-sorted) =================
    {
        int gw = tid >> 5, l = t & 31, wl = t >> 5;
        int h = l >> 3, q = l & 7;                 // 4 nodes/warp, 8 lanes/node
        int nw = G * 8;
        const float4* F4 = (const float4*)g_Wh;    // row = 8 float4 (64 halves)
        float4 bq0 = __ldg(&((const float4*)MLPb)[q * 2]);
        float4 bq1 = __ldg(&((const float4*)MLPb)[q * 2 + 1]);
        double ddt = 0.0;
        for (int pw = gw; pw < NN / 4; pw += nw) {
            int w = __ldg(&g_ord[pw * 4 + h]);     // 4 consecutive sorted nodes -> matched degree
            int s = g_ptr[w], e = g_ptr[w + 1];
            float a[8] = {};
            int i = s;
            for (; i + 4 <= e; i += 4) {
                int s0 = __ldg(&g_srt[i]),     s1 = __ldg(&g_srt[i + 1]);
                int s2 = __ldg(&g_srt[i + 2]), s3 = __ldg(&g_srt[i + 3]);
                float4 u0 = __ldg(&F4[(size_t)s0 * 8 + q]);
                float4 u1 = __ldg(&F4[(size_t)s1 * 8 + q]);
                float4 u2 = __ldg(&F4[(size_t)s2 * 8 + q]);
                float4 u3 = __ldg(&F4[(size_t)s3 * 8 + q]);
                float p0[8], p1[8], p2[8], p3[8];
                cvt8(u0, p0); cvt8(u1, p1); cvt8(u2, p2); cvt8(u3, p3);
                #pragma unroll
                for (int k = 0; k < 8; k++) a[k] += (p0[k] + p1[k]) + (p2[k] + p3[k]);
            }
            for (; i < e; i++) {
                int s0 = __ldg(&g_srt[i]);
                float4 u = __ldg(&F4[(size_t)s0 * 8 + q]);
                float p[8];
                cvt8(u, p);
                #pragma unroll
                for (int k = 0; k < 8; k++) a[k] += p[k];
            }
            a[0] += bq0.x; a[1] += bq0.y; a[2] += bq0.z; a[3] += bq0.w;
            a[4] += bq1.x; a[5] += bq1.y; a[6] += bq1.z; a[7] += bq1.w;
            float m = a[0];
            #pragma unroll
            for (int k = 1; k < 8; k++) m = fmaxf(m, a[k]);
            #pragma unroll
            for (int d = 4; d >= 1; d >>= 1) m = fmaxf(m, __shfl_xor_sync(0xffffffffu, m, d));
            float ex[8], sum = 0.f;
            #pragma unroll
            for (int k = 0; k < 8; k++) { ex[k] = expf(a[k] - m); sum += ex[k]; }
            #pragma unroll
            for (int d = 4; d >= 1; d >>= 1) sum += __shfl_xor_sync(0xffffffffu, sum, d);
            float inv = 1.f / sum;
            float v[8];
            float ssq = 0.f;
            #pragma unroll
            for (int k = 0; k < 8; k++) { v[k] = ex[k] * inv; ssq += v[k] * v[k]; }
            ((float4*)g_S)[(size_t)w * 16 + q * 2]     = make_float4(v[0], v[1], v[2], v[3]);
            ((float4*)g_S)[(size_t)w * 16 + q * 2 + 1] = make_float4(v[4], v[5], v[6], v[7]);
            __half2 h0 = __floats2half2_rn(v[0], v[1]);
            __half2 h1 = __floats2half2_rn(v[2], v[3]);
            __half2 h2 = __floats2half2_rn(v[4], v[5]);
            __half2 h3 = __floats2half2_rn(v[6], v[7]);
            ((float4*)g_Sh)[(size_t)w * 8 + q] =
                make_float4(*(float*)&h0, *(float*)&h1, *(float*)&h2, *(float*)&h3);
            #pragma unroll
            for (int d = 4; d >= 1; d >>= 1) ssq += __shfl_xor_sync(0xffffffffu, ssq, d);
            if (q == 0) ddt += (double)(e - s) * (double)ssq;
        }
        __syncthreads();
        if (q == 0) s_red[wl * 4 + h] = ddt;
        __syncthreads();
        if (t == 0) {
            double a = 0.0;
            #pragma unroll
            for (int z = 0; z < 32; z++) a += s_red[z];
            atomicAdd(&g_dt, a);
        }
    }
    gsync(5u * G);

    // ================= P5: cut = sum_e S[row_e] . S[col_e]  (edge-parallel, 8 lanes/edge) =================
    {
        int q = t & 7;
        int gq = tid >> 3;
        int ngr = (int)G * 32;
        const float4* F4 = (const float4*)g_Sh;
        float acc = 0.f;
        for (int e = gq; e < EE; e += ngr) {
            int r = __ldg(&row[e]);
            int c = __ldg(&col[e]);
            float4 u = __ldg(&F4[(size_t)r * 8 + q]);
            float4 v = __ldg(&F4[(size_t)c * 8 + q]);
            float pu[8], pv[8];
            cvt8(u, pu); cvt8(v, pv);
            float d = 0.f;
            #pragma unroll
            for (int k = 0; k < 8; k++) d += pu[k] * pv[k];
            acc += d;
        }
        #pragma unroll
        for (int d = 16; d >= 1; d >>= 1) acc += __shfl_xor_sync(0xffffffffu, acc, d);
        __syncthreads();
        if ((t & 31) == 0) s_red[t >> 5] = (double)acc;
        __syncthreads();
        if (t == 0) {
            double a = 0.0;
            #pragma unroll
            for (int z = 0; z < 8; z++) a += s_red[z];
            atomicAdd(&g_cut, a);
        }
    }
    gsync(6u * G);

    // ================= P6: SSmat (blocks < ssp) | final (rest) =================
    {
        int ssp = (G >= 512u) ? 256 : (int)(G / 2);
        if (bid < ssp) {
            int ti = t >> 4, tj = t & 15;
            float acc[4][4] = {};
            const float4* S4 = (const float4*)g_S;
            for (int rb = bid * 16; rb < NN; rb += ssp * 16) {
                __syncthreads();
                s_rows[t >> 4][t & 15] = S4[(size_t)(rb + (t >> 4)) * 16 + (t & 15)];
                __syncthreads();
                #pragma unroll 4
                for (int r = 0; r < 16; r++) {
                    float4 a = s_rows[r][ti];
                    float4 c = s_rows[r][tj];
                    acc[0][0] += a.x * c.x; acc[0][1] += a.x * c.y; acc[0][2] += a.x * c.z; acc[0][3] += a.x * c.w;
                    acc[1][0] += a.y * c.x; acc[1][1] += a.y * c.y; acc[1][2] += a.y * c.z; acc[1][3] += a.y * c.w;
                    acc[2][0] += a.z * c.x; acc[2][1] += a.z * c.y; acc[2][2] += a.z * c.z; acc[2][3] += a.z * c.w;
                    acc[3][0] += a.w * c.x; acc[3][1] += a.w * c.y; acc[3][2] += a.w * c.z; acc[3][3] += a.w * c.w;
                }
            }
            #pragma unroll
            for (int p = 0; p < 4; p++)
                #pragma unroll
                for (int qq = 0; qq < 4; qq++)
                    atomicAdd(&g_SS[(ti * 4 + p) * KE + tj * 4 + qq], acc[p][qq]);
        } else {
            for (int idx = t; idx < 512; idx += 256) {
                int c4 = idx >> 4, o = idx & 15;
                s_Wx[c4][o] = ((const float4*)g_Wc)[o * 32 + c4];
            }
            {
                int k4 = t >> 4, o = t & 15;
                s_Wa[k4][o] = ((const float4*)finW)[o * 80 + 64 + k4];
            }
            if (t < 16) s_bo[t] = g_bc[t];
            __syncthreads();
            const float4* x4 = (const float4*)x;
            const float4* S4 = (const float4*)g_S;
            for (int g = bid - ssp; g < 6250; g += (int)G - ssp) {
                int n = g * 16 + (t >> 4);
                int o = t & 15;
                float acc = s_bo[o];
                #pragma unroll 8
                for (int c4 = 0; c4 < 32; c4++) {
                    float4 xv = x4[(size_t)n * 32 + c4];
                    float4 wv = s_Wx[c4][o];
                    acc += xv.x * wv.x + xv.y * wv.y + xv.z * wv.z + xv.w * wv.w;
                }
                #pragma unroll 8
                for (int k4 = 0; k4 < 16; k4++) {
                    float4 sv = S4[(size_t)n * 16 + k4];
                    float4 wv = s_Wa[k4][o];
                    acc += sv.x * wv.x + sv.y * wv.y + sv.z * wv.z + sv.w * wv.w;
                }
                float m = acc;
                #pragma unroll
                for (int d = 1; d < 16; d <<= 1) m = fmaxf(m, __shfl_xor_sync(0xffffffffu, m, d));
                float ex = expf(acc - m);
                float sum = ex;
                #pragma unroll
                for (int d = 1; d < 16; d <<= 1) sum += __shfl_xor_sync(0xffffffffu, sum, d);
                out[(size_t)n * 16 + o] = acc - m - logf(sum);
            }
        }
    }
    gsync(7u * G);

    // ================= P7: loss (block 0) =================
    if (bid == 0) {
        double s = 0.0;
        for (int i = t; i < KE * KE; i += 256) { double v = (double)g_SS[i]; s += v * v; }
        s_loss[t] = s; __syncthreads();
        for (int off = 128; off >= 1; off >>= 1) { if (t < off) s_loss[t] += s_loss[t + off]; __syncthreads(); }
        if (t == 0) s_dnrm = sqrt(s_loss[0]);
        __syncthreads();
        double s2 = 0.0;
        for (int i = t; i < KE * KE; i += 256) {
            double v = (double)g_SS[i] / s_dnrm;
            if ((i >> 6) == (i & 63)) v -= 0.125;   // I / sqrt(64)
            s2 += v * v;
        }
        s_loss[t] = s2; __syncthreads();
        for (int off = 128; off >= 1; off >>= 1) { if (t < off) s_loss[t] += s_loss[t + off]; __syncthreads(); }
        if (t == 0) {
            double loss = -(g_cut / g_dt) + sqrt(s_loss[0]);
            out[outIdx] = (float)loss;
        }
    }
}

// ================================================================ launch
extern "C" void kernel_launch(void* const* d_in, const int* in_sizes, int n_in,
                              void* d_out, int out_size) {
    const float* x     = (const float*)d_in[0];
    const int*   ei    = (const int*)  d_in[1];
    const float* MLPW  = (const float*)d_in[2];
    const float* MLPb  = (const float*)d_in[3];
    const float* mlpxW = (const float*)d_in[4];
    const float* mlpxb = (const float*)d_in[5];
    const float* finW  = (const float*)d_in[6];
    const float* finb  = (const float*)d_in[7];
    float* out = (float*)d_out;

    const int* row = ei;
    const int* col = ei + EE;

    int nb = 0;
    cudaOccupancyMaxActiveBlocksPerMultiprocessor(&nb, k_persist, 256, 0);
    if (nb <= 0) nb = 1;
    int smc = 0;
    cudaDeviceGetAttribute(&smc, cudaDevAttrMultiProcessorCount, 0);
    if (smc <= 0) smc = 148;
    unsigned G = (unsigned)(nb * smc);
    if (G > 2048u) G = 2048u;

    void* degp = nullptr;  cudaGetSymbolAddress(&degp, g_deg);
    void* barp = nullptr;  cudaGetSymbolAddress(&barp, g_bar);
    cudaMemsetAsync(degp, 0, NN * sizeof(int));
    cudaMemsetAsync(barp, 0, sizeof(unsigned));

    k_persist<<<G, 256>>>(MLPW, row, col, MLPb, finW, mlpxW, mlpxb, finb, x, out,
                          out_size - 1);
}

// round 13
// speedup vs baseline: 1.0512x; 1.0512x over previous
#include <cuda_runtime.h>
#include <cuda_fp16.h>
#include <math.h>

#define NN 100000
#define EE 1600000
#define KE 64
#define INC 128
#define HID 256
#define OC 16

// ---- static device scratch ----
__device__ __half  g_Wh[(size_t)NN * KE];  // MLP_W^T fp16 [N,64]
__device__ float   g_S [(size_t)NN * KE];  // S fp32
__device__ __half  g_Sh[(size_t)NN * KE];  // S fp16 (cut-phase gather)
__device__ int     g_deg[NN];
__device__ int     g_ptr[NN + 1];
__device__ int     g_pos[NN];
__device__ int     g_srt[EE];
__device__ int     g_bsum[128];
__device__ float   g_SS[KE * KE];
__device__ float   g_Wc[OC * INC];
__device__ float   g_bc[OC];
__device__ double  g_cut;
__device__ double  g_dt;

__device__ __forceinline__ void cvt8(float4 u, float* p) {
    float2 c0 = __half22float2(*(__half2*)&u.x);
    float2 c1 = __half22float2(*(__half2*)&u.y);
    float2 c2 = __half22float2(*(__half2*)&u.z);
    float2 c3 = __half22float2(*(__half2*)&u.w);
    p[0] = c0.x; p[1] = c0.y; p[2] = c1.x; p[3] = c1.y;
    p[4] = c2.x; p[5] = c2.y; p[6] = c3.x; p[7] = c3.y;
}

// ================================================================ hist (+ zero small)
__global__ void k_hist(const int* __restrict__ col) {
    int e = blockIdx.x * blockDim.x + threadIdx.x;
    if (blockIdx.x == 0) {
        for (int i = threadIdx.x; i < KE * KE; i += 256) g_SS[i] = 0.f;
        if (threadIdx.x == 0) { g_cut = 0.0; g_dt = 0.0; }
    }
    if (e < EE) atomicAdd(&g_deg[col[e]], 1);
}

// ================================================================ transpose MLP_W -> fp16
__global__ void k_transpose(const float* __restrict__ W) {
    __shared__ float tile[32][33];
    int tb = blockIdx.x;
    int v0 = (tb % 3125) * 32, k0 = (tb / 3125) * 32;
    int tx = threadIdx.x & 31, ty = threadIdx.x >> 5;
    #pragma unroll
    for (int r = ty; r < 32; r += 8)
        tile[r][tx] = W[(size_t)(k0 + r) * NN + v0 + tx];
    __syncthreads();
    #pragma unroll
    for (int r = ty; r < 32; r += 8)
        g_Wh[(size_t)(v0 + r) * KE + k0 + tx] = __float2half(tile[tx][r]);
}

// ================================================================ combined weights
__global__ void k_wcomb(const float* __restrict__ finW, const float* __restrict__ mlpxW,
                        const float* __restrict__ mlpxb, const float* __restrict__ finb) {
    int idx = blockIdx.x * blockDim.x + threadIdx.x;
    if (idx < OC * INC) {
        int o = idx >> 7, c = idx & 127;
        float s = 0.f;
        for (int h = 0; h < HID; h++) s += finW[o * 320 + h] * mlpxW[h * INC + c];
        g_Wc[idx] = s;
    }
    if (idx < OC) {
        float s = finb[idx];
        for (int h = 0; h < HID; h++) s += finW[idx * 320 + h] * mlpxb[h];
        g_bc[idx] = s;
    }
}

// ================================================================ scan1
__global__ void k_scan1() {
    __shared__ int sh[256];
    int t = threadIdx.x;
    int base = blockIdx.x * 1024 + t * 4;
    int v0 = (base + 0 < NN) ? g_deg[base + 0] : 0;
    int v1 = (base + 1 < NN) ? g_deg[base + 1] : 0;
    int v2 = (base + 2 < NN) ? g_deg[base + 2] : 0;
    int v3 = (base + 3 < NN) ? g_deg[base + 3] : 0;
    int s = v0 + v1 + v2 + v3;
    sh[t] = s; __syncthreads();
    for (int off = 1; off < 256; off <<= 1) {
        int x = (t >= off) ? sh[t - off] : 0;
        __syncthreads();
        sh[t] += x;
        __syncthreads();
    }
    int run = sh[t] - s;
    if (t == 255) g_bsum[blockIdx.x] = sh[255];
    if (base + 0 < NN) g_ptr[base + 0] = run; run += v0;
    if (base + 1 < NN) g_ptr[base + 1] = run; run += v1;
    if (base + 2 < NN) g_ptr[base + 2] = run; run += v2;
    if (base + 3 < NN) g_ptr[base + 3] = run;
}

// ================================================================ scan23
__global__ void k_scan23(int nblk) {
    __shared__ int sinc[128];
    __shared__ int sexc[128];
    int t = threadIdx.x;
    if (t < 128) sinc[t] = (t < nblk) ? g_bsum[t] : 0;
    __syncthreads();
    for (int off = 1; off < 128; off <<= 1) {
        int x = 0;
        if (t < 128 && t >= off) x = sinc[t - off];
        __syncthreads();
        if (t < 128) sinc[t] += x;
        __syncthreads();
    }
    if (t < 128) sexc[t] = sinc[t] - ((t < nblk) ? g_bsum[t] : 0);
    __syncthreads();
    int i = blockIdx.x * blockDim.x + t;
    if (i < NN) {
        int p = g_ptr[i] + sexc[i >> 10];
        g_ptr[i] = p;
        g_pos[i] = p;
    }
    if (i == 0) g_ptr[NN] = EE;
}

// ================================================================ scatter
__global__ void k_scatter(const int* __restrict__ row, const int* __restrict__ col) {
    int e = blockIdx.x * blockDim.x + threadIdx.x;
    if (e < EE) {
        int p = atomicAdd(&g_pos[col[e]], 1);
        g_srt[p] = row[e];
    }
}

// ================================================================ SpMM1 + softmax + deg_term (quarter-warp/node)
__global__ void __launch_bounds__(256) k_spmm1(const float* __restrict__ MLPb) {
    __shared__ double s_red[32];
    int t = threadIdx.x;
    int l = t & 31, wl = t >> 5;
    int h = l >> 3, q = l & 7;
    int pw = blockIdx.x * 8 + wl;              // global warp id; 3125 blocks x 8 warps = 25000
    const float4* F4 = (const float4*)g_Wh;
    float4 bq0 = __ldg(&((const float4*)MLPb)[q * 2]);
    float4 bq1 = __ldg(&((const float4*)MLPb)[q * 2 + 1]);
    double ddt = 0.0;
    {
        int w = pw * 4 + h;
        int s = g_ptr[w], e = g_ptr[w + 1];
        float a[8] = {};
        int i = s;
        for (; i + 4 <= e; i += 4) {
            int s0 = __ldg(&g_srt[i]),     s1 = __ldg(&g_srt[i + 1]);
            int s2 = __ldg(&g_srt[i + 2]), s3 = __ldg(&g_srt[i + 3]);
            float4 u0 = __ldg(&F4[(size_t)s0 * 8 + q]);
            float4 u1 = __ldg(&F4[(size_t)s1 * 8 + q]);
            float4 u2 = __ldg(&F4[(size_t)s2 * 8 + q]);
            float4 u3 = __ldg(&F4[(size_t)s3 * 8 + q]);
            float p0[8], p1[8], p2[8], p3[8];
            cvt8(u0, p0); cvt8(u1, p1); cvt8(u2, p2); cvt8(u3, p3);
            #pragma unroll
            for (int k = 0; k < 8; k++) a[k] += (p0[k] + p1[k]) + (p2[k] + p3[k]);
        }
        for (; i < e; i++) {
            int s0 = __ldg(&g_srt[i]);
            float4 u = __ldg(&F4[(size_t)s0 * 8 + q]);
            float p[8];
            cvt8(u, p);
            #pragma unroll
            for (int k = 0; k < 8; k++) a[k] += p[k];
        }
        a[0] += bq0.x; a[1] += bq0.y; a[2] += bq0.z; a[3] += bq0.w;
        a[4] += bq1.x; a[5] += bq1.y; a[6] += bq1.z; a[7] += bq1.w;
        float m = a[0];
        #pragma unroll
        for (int k = 1; k < 8; k++) m = fmaxf(m, a[k]);
        #pragma unroll
        for (int d = 4; d >= 1; d >>= 1) m = fmaxf(m, __shfl_xor_sync(0xffffffffu, m, d));
        float ex[8], sum = 0.f;
        #pragma unroll
        for (int k = 0; k < 8; k++) { ex[k] = expf(a[k] - m); sum += ex[k]; }
        #pragma unroll
        for (int d = 4; d >= 1; d >>= 1) sum += __shfl_xor_sync(0xffffffffu, sum, d);
        float inv = 1.f / sum;
        float v[8];
        float ssq = 0.f;
        #pragma unroll
        for (int k = 0; k < 8; k++) { v[k] = ex[k] * inv; ssq += v[k] * v[k]; }
        ((float4*)g_S)[(size_t)w * 16 + q * 2]     = make_float4(v[0], v[1], v[2], v[3]);
        ((float4*)g_S)[(size_t)w * 16 + q * 2 + 1] = make_float4(v[4], v[5], v[6], v[7]);
        __half2 h0 = __floats2half2_rn(v[0], v[1]);
        __half2 h1 = __floats2half2_rn(v[2], v[3]);
        __half2 h2 = __floats2half2_rn(v[4], v[5]);
        __half2 h3 = __floats2half2_rn(v[6], v[7]);
        ((float4*)g_Sh)[(size_t)w * 8 + q] =
            make_float4(*(float*)&h0, *(float*)&h1, *(float*)&h2, *(float*)&h3);
        #pragma unroll
        for (int d = 4; d >= 1; d >>= 1) ssq += __shfl_xor_sync(0xffffffffu, ssq, d);
        if (q == 0) ddt = (double)(e - s) * (double)ssq;
    }
    if (q == 0) s_red[wl * 4 + h] = ddt;
    __syncthreads();
    if (t == 0) {
        double a = 0.0;
        #pragma unroll
        for (int z = 0; z < 32; z++) a += s_red[z];
        atomicAdd(&g_dt, a);
    }
}

// ================================================================ cut = sum_e S[row_e].S[col_e]
__global__ void __launch_bounds__(256) k_cut(const int* __restrict__ row,
                                             const int* __restrict__ col) {
    __shared__ double s_red[8];
    int t = threadIdx.x;
    int q = t & 7;
    int gq = (blockIdx.x * 256 + t) >> 3;
    int ngr = gridDim.x * 32;
    const float4* F4 = (const float4*)g_Sh;
    float acc = 0.f;
    for (int e = gq; e < EE; e += ngr) {
        int r = __ldg(&row[e]);
        int c = __ldg(&col[e]);
        float4 u = __ldg(&F4[(size_t)r * 8 + q]);
        float4 v = __ldg(&F4[(size_t)c * 8 + q]);
        float pu[8], pv[8];
        cvt8(u, pu); cvt8(v, pv);
        float d = 0.f;
        #pragma unroll
        for (int k = 0; k < 8; k++) d += pu[k] * pv[k];
        acc += d;
    }
    #pragma unroll
    for (int d = 16; d >= 1; d >>= 1) acc += __shfl_xor_sync(0xffffffffu, acc, d);
    if ((t & 31) == 0) s_red[t >> 5] = (double)acc;
    __syncthreads();
    if (t == 0) {
        double a = 0.0;
        #pragma unroll
        for (int z = 0; z < 8; z++) a += s_red[z];
        atomicAdd(&g_cut, a);
    }
}

// ================================================================ SS = S^T S
__global__ void __launch_bounds__(256) k_ssmat() {
    __shared__ float4 s_rows[16][16];
    int t = threadIdx.x;
    int ti = t >> 4, tj = t & 15;
    float acc[4][4] = {};
    const float4* S4 = (const float4*)g_S;
    for (int rb = blockIdx.x * 16; rb < NN; rb += gridDim.x * 16) {
        __syncthreads();
        s_rows[t >> 4][t & 15] = S4[(size_t)(rb + (t >> 4)) * 16 + (t & 15)];
        __syncthreads();
        #pragma unroll 4
        for (int r = 0; r < 16; r++) {
            float4 a = s_rows[r][ti];
            float4 c = s_rows[r][tj];
            acc[0][0] += a.x * c.x; acc[0][1] += a.x * c.y; acc[0][2] += a.x * c.z; acc[0][3] += a.x * c.w;
            acc[1][0] += a.y * c.x; acc[1][1] += a.y * c.y; acc[1][2] += a.y * c.z; acc[1][3] += a.y * c.w;
            acc[2][0] += a.z * c.x; acc[2][1] += a.z * c.y; acc[2][2] += a.z * c.z; acc[2][3] += a.z * c.w;
            acc[3][0] += a.w * c.x; acc[3][1] += a.w * c.y; acc[3][2] += a.w * c.z; acc[3][3] += a.w * c.w;
        }
    }
    #pragma unroll
    for (int p = 0; p < 4; p++)
        #pragma unroll
        for (int qq = 0; qq < 4; qq++)
            atomicAdd(&g_SS[(ti * 4 + p) * KE + tj * 4 + qq], acc[p][qq]);
}

// ================================================================ final
__global__ void __launch_bounds__(256) k_final(const float* __restrict__ x,
                                               const float* __restrict__ finW,
                                               float* __restrict__ out) {
    __shared__ float4 s_Wx[32][16];
    __shared__ float4 s_Wa[16][16];
    __shared__ float  s_bo[16];
    int t = threadIdx.x;
    for (int idx = t; idx < 512; idx += 256) {
        int c4 = idx >> 4, o = idx & 15;
        s_Wx[c4][o] = ((const float4*)g_Wc)[o * 32 + c4];
    }
    {
        int k4 = t >> 4, o = t & 15;
        s_Wa[k4][o] = ((const float4*)finW)[o * 80 + 64 + k4];
    }
    if (t < 16) s_bo[t] = g_bc[t];
    __syncthreads();
    const float4* x4 = (const float4*)x;
    const float4* S4 = (const float4*)g_S;
    int n = blockIdx.x * 16 + (t >> 4);
    int o = t & 15;
    float acc = s_bo[o];
    #pragma unroll 8
    for (int c4 = 0; c4 < 32; c4++) {
        float4 xv = x4[(size_t)n * 32 + c4];
        float4 wv = s_Wx[c4][o];
        acc += xv.x * wv.x + xv.y * wv.y + xv.z * wv.z + xv.w * wv.w;
    }
    #pragma unroll 8
    for (int k4 = 0; k4 < 16; k4++) {
        float4 sv = S4[(size_t)n * 16 + k4];
        float4 wv = s_Wa[k4][o];
        acc += sv.x * wv.x + sv.y * wv.y + sv.z * wv.z + sv.w * wv.w;
    }
    float m = acc;
    #pragma unroll
    for (int d = 1; d < 16; d <<= 1) m = fmaxf(m, __shfl_xor_sync(0xffffffffu, m, d));
    float ex = expf(acc - m);
    float sum = ex;
    #pragma unroll
    for (int d = 1; d < 16; d <<= 1) sum += __shfl_xor_sync(0xffffffffu, sum, d);
    out[(size_t)n * 16 + o] = acc - m - logf(sum);
}

// ================================================================ loss
__global__ void k_loss(float* __restrict__ out, int idx) {
    __shared__ double sh[256];
    __shared__ double dnrm;
    int t = threadIdx.x;
    double s = 0.0;
    for (int i = t; i < KE * KE; i += 256) { double v = (double)g_SS[i]; s += v * v; }
    sh[t] = s; __syncthreads();
    for (int off = 128; off >= 1; off >>= 1) { if (t < off) sh[t] += sh[t + off]; __syncthreads(); }
    if (t == 0) dnrm = sqrt(sh[0]);
    __syncthreads();
    double s2 = 0.0;
    for (int i = t; i < KE * KE; i += 256) {
        double v = (double)g_SS[i] / dnrm;
        if ((i >> 6) == (i & 63)) v -= 0.125;   // I / sqrt(64)
        s2 += v * v;
    }
    sh[t] = s2; __syncthreads();
    for (int off = 128; off >= 1; off >>= 1) { if (t < off) sh[t] += sh[t + off]; __syncthreads(); }
    if (t == 0) {
        double loss = -(g_cut / g_dt) + sqrt(sh[0]);
        out[idx] = (float)loss;
    }
}

// ================================================================ launch
extern "C" void kernel_launch(void* const* d_in, const int* in_sizes, int n_in,
                              void* d_out, int out_size) {
    const float* x     = (const float*)d_in[0];
    const int*   ei    = (const int*)  d_in[1];
    const float* MLPW  = (const float*)d_in[2];
    const float* MLPb  = (const float*)d_in[3];
    const float* mlpxW = (const float*)d_in[4];
    const float* mlpxb = (const float*)d_in[5];
    const float* finW  = (const float*)d_in[6];
    const float* finb  = (const float*)d_in[7];
    float* out = (float*)d_out;

    const int* row = ei;
    const int* col = ei + EE;
    const int nblk_scan = (NN + 1023) / 1024;   // 98

    void* degp = nullptr;  cudaGetSymbolAddress(&degp, g_deg);
    cudaMemsetAsync(degp, 0, NN * sizeof(int));

    k_hist<<<EE / 256, 256>>>(col);
    k_transpose<<<6250, 256>>>(MLPW);
    k_wcomb<<<8, 256>>>(finW, mlpxW, mlpxb, finb);
    k_scan1<<<nblk_scan, 256>>>();
    k_scan23<<<(NN + 255) / 256, 256>>>(nblk_scan);
    k_scatter<<<EE / 256, 256>>>(row, col);
    k_spmm1<<<3125, 256>>>(MLPb);          // 8 warps x 4 nodes = 32 nodes/block, exact
    k_cut<<<2048, 256>>>(row, col);
    k_ssmat<<<592, 256>>>();
    k_final<<<6250, 256>>>(x, finW, out);
    k_loss<<<1, 256>>>(out, out_size - 1);
}

// round 14
// speedup vs baseline: 1.1864x; 1.1286x over previous
#include <cuda_runtime.h>
#include <cuda_fp16.h>
#include <math.h>

#define NN 100000
#define EE 1600000
#define KE 64
#define INC 128
#define HID 256
#define OC 16

typedef unsigned long long ull;

// ---- static device scratch ----
__device__ __half  g_Wh[(size_t)NN * KE];  // MLP_W^T fp16 [N,64]
__device__ float   g_S [(size_t)NN * KE];  // S fp32
__device__ ull     g_S8[(size_t)NN * 8];   // S e4m3 rows (64 B) for cut phase
__device__ int     g_deg[NN];
__device__ int     g_ptr[NN + 1];
__device__ int     g_pos[NN];
__device__ int     g_srt[EE];
__device__ int     g_bsum[128];
__device__ float   g_SS[KE * KE];
__device__ float   g_Wc[OC * INC];
__device__ float   g_bc[OC];
__device__ double  g_cut;
__device__ double  g_dt;
__device__ volatile unsigned g_bar;

// ---- software grid barrier: grid <= guaranteed-resident blocks ----
__device__ __forceinline__ void gsync(unsigned target) {
    __syncthreads();
    if (threadIdx.x == 0) {
        __threadfence();
        atomicAdd((unsigned*)&g_bar, 1u);
        while (g_bar < target) __nanosleep(64);
        __threadfence();
    }
    __syncthreads();
}

__device__ __forceinline__ void cvt8(float4 u, float* p) {
    float2 c0 = __half22float2(*(__half2*)&u.x);
    float2 c1 = __half22float2(*(__half2*)&u.y);
    float2 c2 = __half22float2(*(__half2*)&u.z);
    float2 c3 = __half22float2(*(__half2*)&u.w);
    p[0] = c0.x; p[1] = c0.y; p[2] = c1.x; p[3] = c1.y;
    p[4] = c2.x; p[5] = c2.y; p[6] = c3.x; p[7] = c3.y;
}

// ---- e4m3 helpers ----
__device__ __forceinline__ unsigned short f2_to_e4m3x2(float hi, float lo) {
    unsigned short r;
    asm("cvt.rn.satfinite.e4m3x2.f32 %0, %1, %2;" : "=h"(r) : "f"(hi), "f"(lo));
    return r;
}
__device__ __forceinline__ __half2 e4m3x2_to_h2(unsigned short s) {
    unsigned r;
    asm("cvt.rn.f16x2.e4m3x2 %0, %1;" : "=r"(r) : "h"(s));
    return *(__half2*)&r;
}
__device__ __forceinline__ float dotw_e4m3(unsigned a, unsigned b) {
    __half2 a0 = e4m3x2_to_h2((unsigned short)(a & 0xffffu));
    __half2 a1 = e4m3x2_to_h2((unsigned short)(a >> 16));
    __half2 b0 = e4m3x2_to_h2((unsigned short)(b & 0xffffu));
    __half2 b1 = e4m3x2_to_h2((unsigned short)(b >> 16));
    __half2 p = __hmul2(a0, b0);
    p = __hfma2(a1, b1, p);
    float2 f = __half22float2(p);
    return f.x + f.y;
}

__global__ void __launch_bounds__(256) k_persist(
    const float* __restrict__ W,        // MLP_W [64,N]
    const int*   __restrict__ row,
    const int*   __restrict__ col,
    const float* __restrict__ MLPb,
    const float* __restrict__ finW,
    const float* __restrict__ mlpxW,
    const float* __restrict__ mlpxb,
    const float* __restrict__ finb,
    const float* __restrict__ x,
    float*       __restrict__ out,
    int outIdx)
{
    const unsigned G = gridDim.x;
    const int bid = blockIdx.x;
    const int t   = threadIdx.x;
    const int tid = bid * 256 + t;
    const int stride = G * 256;

    __shared__ float  s_tile[32][33];
    __shared__ int    s_scan[256];
    __shared__ int    s_exc[128];
    __shared__ double s_red[32];
    __shared__ float4 s_rows[16][16];
    __shared__ float4 s_Wx[32][16];
    __shared__ float4 s_Wa[16][16];
    __shared__ float  s_bo[16];
    __shared__ double s_loss[256];
    __shared__ double s_dnrm;

    // ================= P0: hist | transpose->fp16 | wcomb | zero small =================
    if (bid == 0) {
        for (int i = t; i < KE * KE; i += 256) g_SS[i] = 0.f;
        if (t == 0) { g_cut = 0.0; g_dt = 0.0; }
    }
    for (int e = tid; e < EE; e += stride) atomicAdd(&g_deg[col[e]], 1);
    for (int tb = bid; tb < 6250; tb += (int)G) {
        int v0 = (tb % 3125) * 32, k0 = (tb / 3125) * 32;
        int tx = t & 31, ty = t >> 5;
        __syncthreads();
        #pragma unroll
        for (int r = ty; r < 32; r += 8)
            s_tile[r][tx] = W[(size_t)(k0 + r) * NN + v0 + tx];
        __syncthreads();
        #pragma unroll
        for (int r = ty; r < 32; r += 8)
            g_Wh[(size_t)(v0 + r) * KE + k0 + tx] = __float2half(s_tile[tx][r]);
    }
    for (int idx = tid; idx < OC * INC; idx += stride) {
        int o = idx >> 7, c = idx & 127;
        float s = 0.f;
        for (int h = 0; h < HID; h++) s += finW[o * 320 + h] * mlpxW[h * INC + c];
        g_Wc[idx] = s;
    }
    if (tid < OC) {
        float s = finb[tid];
        for (int h = 0; h < HID; h++) s += finW[tid * 320 + h] * mlpxb[h];
        g_bc[tid] = s;
    }
    gsync(1u * G);

    // ================= P1: per-chunk scan (98 chunks of 1024) =================
    for (int c = bid; c < 98; c += (int)G) {
        int base = c * 1024 + t * 4;
        int v0 = (base + 0 < NN) ? g_deg[base + 0] : 0;
        int v1 = (base + 1 < NN) ? g_deg[base + 1] : 0;
        int v2 = (base + 2 < NN) ? g_deg[base + 2] : 0;
        int v3 = (base + 3 < NN) ? g_deg[base + 3] : 0;
        int s = v0 + v1 + v2 + v3;
        s_scan[t] = s; __syncthreads();
        for (int off = 1; off < 256; off <<= 1) {
            int xv = (t >= off) ? s_scan[t - off] : 0;
            __syncthreads();
            s_scan[t] += xv;
            __syncthreads();
        }
        int run = s_scan[t] - s;
        if (t == 255) g_bsum[c] = s_scan[255];
        if (base + 0 < NN) g_ptr[base + 0] = run; run += v0;
        if (base + 1 < NN) g_ptr[base + 1] = run; run += v1;
        if (base + 2 < NN) g_ptr[base + 2] = run; run += v2;
        if (base + 3 < NN) g_ptr[base + 3] = run;
    }
    gsync(2u * G);

    // ================= P2: redundant block-sum scan + apply offsets =================
    {
        int v = (t < 98) ? g_bsum[t] : 0;
        if (t < 128) s_scan[t] = v;
        __syncthreads();
        for (int off = 1; off < 128; off <<= 1) {
            int xv = 0;
            if (t < 128 && t >= off) xv = s_scan[t - off];
            __syncthreads();
            if (t < 128) s_scan[t] += xv;
            __syncthreads();
        }
        if (t < 128) s_exc[t] = s_scan[t] - v;
        __syncthreads();
        for (int i = tid; i < NN; i += stride) {
            int p = g_ptr[i] + s_exc[i >> 10];
            g_ptr[i] = p;
            g_pos[i] = p;
        }
        if (tid == 0) g_ptr[NN] = EE;
    }
    gsync(3u * G);

    // ================= P3: scatter edges into CSR =================
    for (int e = tid; e < EE; e += stride) {
        int p = atomicAdd(&g_pos[col[e]], 1);
        g_srt[p] = row[e];
    }
    gsync(4u * G);

    // ================= P4: SpMM1 + softmax + deg_term (quarter-warp/node) =================
    {
        int gw = tid >> 5, l = t & 31, wl = t >> 5;
        int h = l >> 3, q = l & 7;                 // 4 nodes/warp, 8 lanes/node
        int nw = G * 8;
        const float4* F4 = (const float4*)g_Wh;    // row = 8 float4 (64 halves)
        float4 bq0 = __ldg(&((const float4*)MLPb)[q * 2]);
        float4 bq1 = __ldg(&((const float4*)MLPb)[q * 2 + 1]);
        double ddt = 0.0;
        for (int pw = gw; pw < NN / 4; pw += nw) {
            int w = pw * 4 + h;
            int s = g_ptr[w], e = g_ptr[w + 1];
            float a[8] = {};
            int i = s;
            for (; i + 4 <= e; i += 4) {
                int s0 = __ldg(&g_srt[i]),     s1 = __ldg(&g_srt[i + 1]);
                int s2 = __ldg(&g_srt[i + 2]), s3 = __ldg(&g_srt[i + 3]);
                float4 u0 = __ldg(&F4[(size_t)s0 * 8 + q]);
                float4 u1 = __ldg(&F4[(size_t)s1 * 8 + q]);
                float4 u2 = __ldg(&F4[(size_t)s2 * 8 + q]);
                float4 u3 = __ldg(&F4[(size_t)s3 * 8 + q]);
                float p0[8], p1[8], p2[8], p3[8];
                cvt8(u0, p0); cvt8(u1, p1); cvt8(u2, p2); cvt8(u3, p3);
                #pragma unroll
                for (int k = 0; k < 8; k++) a[k] += (p0[k] + p1[k]) + (p2[k] + p3[k]);
            }
            for (; i < e; i++) {
                int s0 = __ldg(&g_srt[i]);
                float4 u = __ldg(&F4[(size_t)s0 * 8 + q]);
                float p[8];
                cvt8(u, p);
                #pragma unroll
                for (int k = 0; k < 8; k++) a[k] += p[k];
            }
            a[0] += bq0.x; a[1] += bq0.y; a[2] += bq0.z; a[3] += bq0.w;
            a[4] += bq1.x; a[5] += bq1.y; a[6] += bq1.z; a[7] += bq1.w;
            float m = a[0];
            #pragma unroll
            for (int k = 1; k < 8; k++) m = fmaxf(m, a[k]);
            #pragma unroll
            for (int d = 4; d >= 1; d >>= 1) m = fmaxf(m, __shfl_xor_sync(0xffffffffu, m, d));
            float ex[8], sum = 0.f;
            #pragma unroll
            for (int k = 0; k < 8; k++) { ex[k] = expf(a[k] - m); sum += ex[k]; }
            #pragma unroll
            for (int d = 4; d >= 1; d >>= 1) sum += __shfl_xor_sync(0xffffffffu, sum, d);
            float inv = 1.f / sum;
            float v[8];
            float ssq = 0.f;
            #pragma unroll
            for (int k = 0; k < 8; k++) { v[k] = ex[k] * inv; ssq += v[k] * v[k]; }
            ((float4*)g_S)[(size_t)w * 16 + q * 2]     = make_float4(v[0], v[1], v[2], v[3]);
            ((float4*)g_S)[(size_t)w * 16 + q * 2 + 1] = make_float4(v[4], v[5], v[6], v[7]);
            // e4m3 packed row (64 B total; this lane contributes 8 bytes)
            unsigned short b0 = f2_to_e4m3x2(v[1], v[0]);
            unsigned short b1 = f2_to_e4m3x2(v[3], v[2]);
            unsigned short b2 = f2_to_e4m3x2(v[5], v[4]);
            unsigned short b3 = f2_to_e4m3x2(v[7], v[6]);
            ull packed = (ull)b0 | ((ull)b1 << 16) | ((ull)b2 << 32) | ((ull)b3 << 48);
            g_S8[(size_t)w * 8 + q] = packed;
            #pragma unroll
            for (int d = 4; d >= 1; d >>= 1) ssq += __shfl_xor_sync(0xffffffffu, ssq, d);
            if (q == 0) ddt += (double)(e - s) * (double)ssq;
        }
        __syncthreads();
        if (q == 0) s_red[wl * 4 + h] = ddt;
        __syncthreads();
        if (t == 0) {
            double a = 0.0;
            #pragma unroll
            for (int z = 0; z < 32; z++) a += s_red[z];
            atomicAdd(&g_dt, a);
        }
    }
    gsync(5u * G);

    // ================= P5: cut = sum_e S[row_e].S[col_e]  (edge-parallel, 8 lanes/edge, e4m3) =================
    {
        int q = t & 7;
        int gq = tid >> 3;
        int ngr = (int)G * 32;
        const uint2* F8 = (const uint2*)g_S8;     // 8 B per lane per row
        float acc = 0.f;
        for (int e = gq; e < EE; e += ngr) {
            int r = __ldg(&row[e]);
            int c = __ldg(&col[e]);
            uint2 ua = __ldg(&F8[(size_t)r * 8 + q]);
            uint2 ub = __ldg(&F8[(size_t)c * 8 + q]);
            acc += dotw_e4m3(ua.x, ub.x) + dotw_e4m3(ua.y, ub.y);
        }
        #pragma unroll
        for (int d = 16; d >= 1; d >>= 1) acc += __shfl_xor_sync(0xffffffffu, acc, d);
        __syncthreads();
        if ((t & 31) == 0) s_red[t >> 5] = (double)acc;
        __syncthreads();
        if (t == 0) {
            double a = 0.0;
            #pragma unroll
            for (int z = 0; z < 8; z++) a += s_red[z];
            atomicAdd(&g_cut, a);
        }
    }
    gsync(6u * G);

    // ================= P6: SSmat (blocks < ssp) | final (rest) =================
    {
        int ssp = (G >= 512u) ? 256 : (int)(G / 2);
        if (bid < ssp) {
            int ti = t >> 4, tj = t & 15;
            float acc[4][4] = {};
            const float4* S4 = (const float4*)g_S;
            for (int rb = bid * 16; rb < NN; rb += ssp * 16) {
                __syncthreads();
                s_rows[t >> 4][t & 15] = S4[(size_t)(rb + (t >> 4)) * 16 + (t & 15)];
                __syncthreads();
                #pragma unroll 4
                for (int r = 0; r < 16; r++) {
                    float4 a = s_rows[r][ti];
                    float4 c = s_rows[r][tj];
                    acc[0][0] += a.x * c.x; acc[0][1] += a.x * c.y; acc[0][2] += a.x * c.z; acc[0][3] += a.x * c.w;
                    acc[1][0] += a.y * c.x; acc[1][1] += a.y * c.y; acc[1][2] += a.y * c.z; acc[1][3] += a.y * c.w;
                    acc[2][0] += a.z * c.x; acc[2][1] += a.z * c.y; acc[2][2] += a.z * c.z; acc[2][3] += a.z * c.w;
                    acc[3][0] += a.w * c.x; acc[3][1] += a.w * c.y; acc[3][2] += a.w * c.z; acc[3][3] += a.w * c.w;
                }
            }
            #pragma unroll
            for (int p = 0; p < 4; p++)
                #pragma unroll
                for (int qq = 0; qq < 4; qq++)
                    atomicAdd(&g_SS[(ti * 4 + p) * KE + tj * 4 + qq], acc[p][qq]);
        } else {
            for (int idx = t; idx < 512; idx += 256) {
                int c4 = idx >> 4, o = idx & 15;
                s_Wx[c4][o] = ((const float4*)g_Wc)[o * 32 + c4];
            }
            {
                int k4 = t >> 4, o = t & 15;
                s_Wa[k4][o] = ((const float4*)finW)[o * 80 + 64 + k4];
            }
            if (t < 16) s_bo[t] = g_bc[t];
            __syncthreads();
            const float4* x4 = (const float4*)x;
            const float4* S4 = (const float4*)g_S;
            for (int g = bid - ssp; g < 6250; g += (int)G - ssp) {
                int n = g * 16 + (t >> 4);
                int o = t & 15;
                float acc = s_bo[o];
                #pragma unroll 8
                for (int c4 = 0; c4 < 32; c4++) {
                    float4 xv = x4[(size_t)n * 32 + c4];
                    float4 wv = s_Wx[c4][o];
                    acc += xv.x * wv.x + xv.y * wv.y + xv.z * wv.z + xv.w * wv.w;
                }
                #pragma unroll 8
                for (int k4 = 0; k4 < 16; k4++) {
                    float4 sv = S4[(size_t)n * 16 + k4];
                    float4 wv = s_Wa[k4][o];
                    acc += sv.x * wv.x + sv.y * wv.y + sv.z * wv.z + sv.w * wv.w;
                }
                float m = acc;
                #pragma unroll
                for (int d = 1; d < 16; d <<= 1) m = fmaxf(m, __shfl_xor_sync(0xffffffffu, m, d));
                float ex = expf(acc - m);
                float sum = ex;
                #pragma unroll
                for (int d = 1; d < 16; d <<= 1) sum += __shfl_xor_sync(0xffffffffu, sum, d);
                out[(size_t)n * 16 + o] = acc - m - logf(sum);
            }
        }
    }
    gsync(7u * G);

    // ================= P7: loss (block 0) =================
    if (bid == 0) {
        double s = 0.0;
        for (int i = t; i < KE * KE; i += 256) { double v = (double)g_SS[i]; s += v * v; }
        s_loss[t] = s; __syncthreads();
        for (int off = 128; off >= 1; off >>= 1) { if (t < off) s_loss[t] += s_loss[t + off]; __syncthreads(); }
        if (t == 0) s_dnrm = sqrt(s_loss[0]);
        __syncthreads();
        double s2 = 0.0;
        for (int i = t; i < KE * KE; i += 256) {
            double v = (double)g_SS[i] / s_dnrm;
            if ((i >> 6) == (i & 63)) v -= 0.125;   // I / sqrt(64)
            s2 += v * v;
        }
        s_loss[t] = s2; __syncthreads();
        for (int off = 128; off >= 1; off >>= 1) { if (t < off) s_loss[t] += s_loss[t + off]; __syncthreads(); }
        if (t == 0) {
            double loss = -(g_cut / g_dt) + sqrt(s_loss[0]);
            out[outIdx] = (float)loss;
        }
    }
}

// ================================================================ launch
extern "C" void kernel_launch(void* const* d_in, const int* in_sizes, int n_in,
                              void* d_out, int out_size) {
    const float* x     = (const float*)d_in[0];
    const int*   ei    = (const int*)  d_in[1];
    const float* MLPW  = (const float*)d_in[2];
    const float* MLPb  = (const float*)d_in[3];
    const float* mlpxW = (const float*)d_in[4];
    const float* mlpxb = (const float*)d_in[5];
    const float* finW  = (const float*)d_in[6];
    const float* finb  = (const float*)d_in[7];
    float* out = (float*)d_out;

    const int* row = ei;
    const int* col = ei + EE;

    int nb = 0;
    cudaOccupancyMaxActiveBlocksPerMultiprocessor(&nb, k_persist, 256, 0);
    if (nb <= 0) nb = 1;
    int smc = 0;
    cudaDeviceGetAttribute(&smc, cudaDevAttrMultiProcessorCount, 0);
    if (smc <= 0) smc = 148;
    unsigned G = (unsigned)(nb * smc);
    if (G > 2048u) G = 2048u;

    void* degp = nullptr;  cudaGetSymbolAddress(&degp, g_deg);
    void* barp = nullptr;  cudaGetSymbolAddress(&barp, g_bar);
    cudaMemsetAsync(degp, 0, NN * sizeof(int));
    cudaMemsetAsync(barp, 0, sizeof(unsigned));

    k_persist<<<G, 256>>>(MLPW, row, col, MLPb, finW, mlpxW, mlpxb, finb, x, out,
                          out_size - 1);
}